// round 11
// baseline (speedup 1.0000x reference)
#include <cuda_runtime.h>
#include <cuda_bf16.h>

#define NB 8
#define BQ 512
#define EPSF 1e-7f
#define ROWS_PER_BLK 32
#define BLKS_PER_B (BQ / ROWS_PER_BLK)   // 16

typedef unsigned long long u64;

// ---------------- device scratch (no allocations allowed; zero-initialized) ----------------
__device__ u64    g_ones[NB * BQ * 8];   // cost bitset: bit j of row i set iff gl[b,i,j] < 0.2
__device__ u64    g_info[NB * BQ];       // per-row: n(3b) | c0..c3 (10b each) | diag<<43
__device__ float  g_part[NB];            // ciou partial sums
__device__ unsigned g_done[NB];          // per-batch phase-1 completion (self-resetting)
__device__ unsigned g_ctr;               // final completion counter (self-resetting)

// general-JV fallback scratch (practically never used)
__device__ int   fbU[NB][BQ + 1], fbV[NB][BQ + 1], fbMinv[NB][BQ + 1];
__device__ short fbWay[NB][BQ + 1], fbP1[NB][BQ + 1];
__device__ unsigned char fbUsed[NB][BQ + 1];

// Kalman filter is an exact identity on the mean: filtered = (prev*scale)/scale
__device__ __forceinline__ float4 xyxy_filtered(float4 pb, float W, float H) {
    float f0 = (pb.x * W) / W;
    float f1 = (pb.y * H) / H;
    float f2 = (pb.z * W) / W;
    float f3 = (pb.w * H) / H;
    return make_float4(f0 - 0.5f * f2, f1 - 0.5f * f3, f0 + 0.5f * f2, f1 + 0.5f * f3);
}
__device__ __forceinline__ float4 xyxy(float4 v) {
    return make_float4(v.x - 0.5f * v.z, v.y - 0.5f * v.w, v.x + 0.5f * v.z, v.y + 0.5f * v.w);
}

// ================= single fused kernel =================
// Phase 1 (all 128 blocks): pairwise giou threshold -> bitset + packed row info.
// Phase 2 (last block of each batch): Hungarian (exact JV) + CIoU partial.
// Phase 3 (last finishing thread): final mean.
__global__ void __launch_bounds__(BQ) k_fused(const float4* __restrict__ prev,
                                              const float4* __restrict__ curr,
                                              const float2* __restrict__ sizes,
                                              float* __restrict__ out) {
    int b = blockIdx.y;
    int i0 = blockIdx.x * ROWS_PER_BLK;
    int tid = threadIdx.x;

    __shared__ float4 sa[ROWS_PER_BLK];
    __shared__ float  sArea[ROWS_PER_BLK];
    __shared__ unsigned sMask[ROWS_PER_BLK * 16];
    __shared__ int sLast;
    // phase-2 storage
    __shared__ u64 sInfo[BQ];
    __shared__ u64 sDiag[8];
    __shared__ u64 fMask[8];
    __shared__ short p_[BQ];
    __shared__ short colOfRow[BQ];
    __shared__ unsigned wayTag[BQ];
    __shared__ float swr[16];

    float2 s = sizes[b];

    // ---------------- phase 1: cost bitset + row info ----------------
    if (tid < ROWS_PER_BLK) {
        float4 a = xyxy(curr[b * BQ + i0 + tid]);
        sa[tid] = a;
        sArea[tid] = (a.z - a.x) * (a.w - a.y);
    }
    float4 c = xyxy_filtered(prev[b * BQ + tid], s.y, s.x);
    float area_b = (c.z - c.x) * (c.w - c.y);
    __syncthreads();
    unsigned lane = tid & 31, warp = tid >> 5;
#pragma unroll 4
    for (int r = 0; r < ROWS_PER_BLK; r++) {
        float4 a = sa[r];
        float area_a = sArea[r];
        float ltx = fmaxf(a.x, c.x), lty = fmaxf(a.y, c.y);
        float rbx = fminf(a.z, c.z), rby = fminf(a.w, c.w);
        float wx = fmaxf(rbx - ltx, 0.0f), wy = fmaxf(rby - lty, 0.0f);
        float I = wx * wy;
        float U = area_a + area_b - I;
        float p = U + EPSF;
        // necessary condition (C >= U): pred => I > 0.8*p; 0.79 slack absorbs rounding
        unsigned anyb = __ballot_sync(0xffffffffu, I > 0.79f * p);
        unsigned m = 0u;
        if (anyb) {   // warp-uniform
            float lcx = fminf(a.x, c.x), lcy = fminf(a.y, c.y);
            float rcx = fmaxf(a.z, c.z), rcy = fmaxf(a.w, c.w);
            float C = (rcx - lcx) * (rcy - lcy);
            float q = C + EPSF;
            bool pred = (I * q - (C - U) * p) > (0.8f * p) * q;
            m = __ballot_sync(0xffffffffu, pred);
        }
        if (lane == 0) {
            sMask[r * 16 + warp] = m;
            ((unsigned*)g_ones)[((size_t)(b * BQ + i0 + r)) * 16 + warp] = m;
        }
    }
    __syncthreads();
    if (tid < ROWS_PER_BLK) {
        int gi = i0 + tid;
        int n = 0, c0v = 0, c1v = 0, c2v = 0, c3v = 0;
#pragma unroll
        for (int k = 0; k < 16; k++) {
            unsigned x = sMask[tid * 16 + k];
            while (x) {
                int cc = (k << 5) + __ffs(x) - 1;
                if (n == 0) c0v = cc; else if (n == 1) c1v = cc;
                else if (n == 2) c2v = cc; else if (n == 3) c3v = cc;
                n++;
                x &= x - 1;
            }
        }
        if (n > 4) n = 5;
        u64 diag = (u64)((sMask[tid * 16 + (gi >> 5)] >> (gi & 31)) & 1u);
        g_info[b * BQ + gi] = (u64)n | ((u64)c0v << 3) | ((u64)c1v << 13)
                            | ((u64)c2v << 23) | ((u64)c3v << 33) | (diag << 43);
    }
    __syncthreads();

    // ---------------- handoff: last block of this batch continues ----------------
    if (tid == 0) {
        __threadfence();
        unsigned old = atomicAdd(&g_done[b], 1u);
        sLast = (old == BLKS_PER_B - 1);
        if (sLast) g_done[b] = 0u;   // self-reset for graph replay
    }
    __syncthreads();
    if (!sLast) return;
    __threadfence();                 // acquire: all phase-1 writes of this batch visible

    // ---------------- phase 2: Hungarian (exact JV) ----------------
    const u64* ones = g_ones + (size_t)b * BQ * 8;

    u64 info = g_info[b * BQ + tid];       // one coalesced LDG.64 (L2-hot)
    sInfo[tid] = info;
    p_[tid] = (short)tid;                  // default: identity (exact for all non-diag rows)
    wayTag[tid] = 0u;
    {
        bool diag = ((info >> 43) & 1ULL) != 0ULL;
        unsigned bal = __ballot_sync(0xffffffffu, diag);
        if ((tid & 31) == 0) ((unsigned*)sDiag)[tid >> 5] = bal;
    }
    __syncthreads();

    if (tid == 0) {
        int toRow = -1;
        // ---- serial: diagonal rows only ----
        for (int w = 0; w < 8 && toRow < 0; w++) {
            u64 m = sDiag[w];
            while (m) {
                int i = (w << 6) + __ffsll((long long)m) - 1;
                m &= m - 1;
                u64 ri = sInfo[i];
                int ni = (int)(ri & 7u);
                if (ni >= 5) { toRow = i; break; }
                int i0c = (int)((ri >> 3) & 1023u);
                int i1c = (int)((ri >> 13) & 1023u);
                int i2c = (int)((ri >> 23) & 1023u);
                int i3c = (int)((ri >> 33) & 1023u);
                // a = first column in 0..4 not in S (list sorted ascending)
                int a = 0;
                if (i0c == 0) {
                    a = 1;
                    if (ni > 1 && i1c == 1) { a = 2;
                        if (ni > 2 && i2c == 2) { a = 3;
                            if (ni > 3 && i3c == 3) a = 4; } }
                }
                if (a >= i) { toRow = i; break; }      // partner col not yet assigned
                int h = p_[a];                          // current holder of col a
                u64 hi = sInfo[h];
                int nh = (int)(hi & 7u);
                if (nh >= 5) { toRow = i; break; }
                int h0 = (int)((hi >> 3) & 1023u);
                int h1 = (int)((hi >> 13) & 1023u);
                int h2 = (int)((hi >> 23) & 1023u);
                int h3 = (int)((hi >> 33) & 1023u);
                bool inter = false;
                if (nh > 0) inter |= (i0c == h0) | (ni > 1 && i1c == h0) | (ni > 2 && i2c == h0) | (ni > 3 && i3c == h0);
                if (nh > 1) inter |= (i0c == h1) | (ni > 1 && i1c == h1) | (ni > 2 && i2c == h1) | (ni > 3 && i3c == h1);
                if (nh > 2) inter |= (i0c == h2) | (ni > 1 && i1c == h2) | (ni > 2 && i2c == h2) | (ni > 3 && i3c == h2);
                if (nh > 3) inter |= (i0c == h3) | (ni > 1 && i1c == h3) | (ni > 2 && i2c == h3) | (ni > 3 && i3c == h3);
                if (inter) { toRow = i; break; }
                // exact closed form of the walk for a conforming diagonal row: swap
                p_[a] = (short)i;
                p_[i] = (short)h;
            }
        }

        if (toRow >= 0) {
            // ================= serial takeover from row toRow (exact R8 machinery) =================
            for (int cc = toRow; cc < BQ; cc++) p_[cc] = -1;
            int tw = toRow >> 6;
            for (int w = 0; w < 8; w++)
                fMask[w] = (w < tw) ? 0ULL : (w == tw ? (~0ULL << (toRow & 63)) : ~0ULL);
            int w0 = tw;
            u64 fw = fMask[w0];
            int p0 = -1, p0n = 0, p0c0 = 0, p0c1 = 0, p0c2 = 0, p0c3 = 0;
            if (toRow > 0) {
                p0 = p_[0];
                u64 ri = sInfo[p0];
                p0n = (int)(ri & 7u);
                p0c0 = (int)((ri >> 3) & 1023u); p0c1 = (int)((ri >> 13) & 1023u);
                p0c2 = (int)((ri >> 23) & 1023u); p0c3 = (int)((ri >> 33) & 1023u);
            }
            int genFb = 0;
            for (int i = toRow; i < BQ && !genFb; i++) {
                u64 ii = sInfo[i];
                int n = (int)(ii & 7u);
                if (n == 0) {
                    while (!fw) { fMask[w0] = 0ULL; fw = fMask[++w0]; }
                    int F = (w0 << 6) + __ffsll((long long)fw) - 1;
                    fw &= fw - 1;
                    p_[F] = (short)i;
                    if (F == 0) { p0 = i; p0n = 0; }
                    continue;
                }
                int c0 = (int)((ii >> 3) & 1023u);
                int c1 = (int)((ii >> 13) & 1023u);
                int c2 = (int)((ii >> 23) & 1023u);
                int c3 = (int)((ii >> 33) & 1023u);
                if (n <= 4 && c0 != 0 && p0 >= 0 && p0n <= 4) {
                    bool inter = false;
                    if (p0n > 0) inter |= (c0 == p0c0) | (n > 1 && c1 == p0c0) | (n > 2 && c2 == p0c0) | (n > 3 && c3 == p0c0);
                    if (p0n > 1) inter |= (c0 == p0c1) | (n > 1 && c1 == p0c1) | (n > 2 && c2 == p0c1) | (n > 3 && c3 == p0c1);
                    if (p0n > 2) inter |= (c0 == p0c2) | (n > 1 && c1 == p0c2) | (n > 2 && c2 == p0c2) | (n > 3 && c3 == p0c2);
                    if (p0n > 3) inter |= (c0 == p0c3) | (n > 1 && c1 == p0c3) | (n > 2 && c2 == p0c3) | (n > 3 && c3 == p0c3);
                    if (!inter) {
                        while (!fw) { fMask[w0] = 0ULL; fw = fMask[++w0]; }
                        int F = (w0 << 6) + __ffsll((long long)fw) - 1;
                        fw &= fw - 1;
                        bool FinS = (F == c0) | (n > 1 && F == c1) | (n > 2 && F == c2) | (n > 3 && F == c3);
                        if (FinS) {
                            p_[F] = (short)p0;
                            p_[0] = (short)i;
                            p0 = i; p0n = n;
                            p0c0 = c0; p0c1 = c1; p0c2 = c2; p0c3 = c3;
                        } else {
                            p_[F] = (short)i;
                        }
                        continue;
                    }
                }
                // slow path: exact JV walk (delta==0 regime), bitsets from L2
                fMask[w0] = fw;
                const u64* rowi = ones + (size_t)i * 8;
                u64 nz[8], U[8];
#pragma unroll
                for (int w = 0; w < 8; w++) { nz[w] = rowi[w]; U[w] = 0ULL; }
                unsigned ep = (unsigned)(i + 1);
                int jf = -1; bool fb = false;
                while (true) {
                    u64 any = 0ULL;
#pragma unroll
                    for (int w = 0; w < 8; w++) any |= nz[w];
                    if (!any) {
#pragma unroll
                        for (int w = 0; w < 8; w++)
                            if (jf < 0 && fMask[w]) jf = w * 64 + __ffsll((long long)fMask[w]) - 1;
                        break;
                    }
                    int j1 = -1;
#pragma unroll
                    for (int w = 0; w < 8; w++) {
                        u64 cnd = ~(U[w] | nz[w]);
                        if (j1 < 0 && cnd) j1 = w * 64 + __ffsll((long long)cnd) - 1;
                    }
                    if (j1 < 0) { fb = true; break; }      // delta>0 would be needed
                    if (p_[j1] < 0) { jf = j1; break; }    // reached a free column
                    U[j1 >> 6] |= 1ULL << (j1 & 63);
                    const u64* rowr = ones + (size_t)p_[j1] * 8;
#pragma unroll
                    for (int w = 0; w < 8; w++) {
                        u64 rw = rowr[w];
                        u64 d = nz[w] & ~rw;
                        while (d) {
                            int cc = w * 64 + __ffsll((long long)d) - 1;
                            wayTag[cc] = (ep << 16) | (unsigned)j1;
                            d &= d - 1;
                        }
                        nz[w] &= rw;
                    }
                }
                if (fb) { genFb = 1; break; }
                fMask[jf >> 6] &= ~(1ULL << (jf & 63));
                int j = jf;
                while (true) {
                    unsigned tg = wayTag[j];
                    if ((tg >> 16) == ep) { int w = (int)(tg & 0xffffu); p_[j] = p_[w]; j = w; }
                    else { p_[j] = (short)i; break; }
                }
                fw = fMask[w0];
                {
                    int r = p_[0];
                    p0 = r;
                    if (r >= 0) {
                        u64 ri = sInfo[r];
                        p0n = (int)(ri & 7u);
                        p0c0 = (int)((ri >> 3) & 1023u); p0c1 = (int)((ri >> 13) & 1023u);
                        p0c2 = (int)((ri >> 23) & 1023u); p0c3 = (int)((ri >> 33) & 1023u);
                    }
                }
            }

            if (genFb) {
                // ---- general JV from scratch (exact numpy semantics) ----
                int*   u_ = fbU[b]; int* v_ = fbV[b]; int* minv_ = fbMinv[b];
                short* way2 = fbWay[b]; short* p1 = fbP1[b];
                unsigned char* used_ = fbUsed[b];
                for (int j = 0; j <= BQ; j++) { u_[j] = 0; v_[j] = 0; p1[j] = 0; }
                const int INF = 0x3f3f3f3f;
                for (int i = 1; i <= BQ; i++) {
                    p1[0] = (short)i; int j0 = 0;
                    for (int j = 0; j <= BQ; j++) { minv_[j] = INF; used_[j] = 0; }
                    while (true) {
                        used_[j0] = 1;
                        int i0p = p1[j0];
                        int d = INF, j1 = -1;
                        int ui = u_[i0p];
                        const u64* rr = ones + (size_t)(i0p - 1) * 8;
                        for (int j = 1; j <= BQ; j++) {
                            if (used_[j]) continue;
                            int cc = j - 1;
                            int cbit = (int)((rr[cc >> 6] >> (cc & 63)) & 1ULL);
                            int cur = cbit - ui - v_[j];
                            if (cur < minv_[j]) { minv_[j] = cur; way2[j] = (short)j0; }
                            if (minv_[j] < d) { d = minv_[j]; j1 = j; }
                        }
                        for (int j = 0; j <= BQ; j++) {
                            if (used_[j]) { u_[p1[j]] += d; v_[j] -= d; }
                            else minv_[j] -= d;
                        }
                        j0 = j1;
                        if (p1[j0] == 0) break;
                    }
                    while (j0) { int jw = way2[j0]; p1[j0] = p1[jw]; j0 = jw; }
                }
                for (int j = 0; j < BQ; j++) p_[j] = (short)(p1[j + 1] - 1);
            }
        }
    }
    __syncthreads();
    colOfRow[p_[tid]] = (short)tid;
    __syncthreads();

    // ---------------- phase 2b: CIoU mean ----------------
    const float C4PI = (float)(4.0 / (3.14159265358979323846 * 3.14159265358979323846));
    int col = colOfRow[tid];
    float4 P = xyxy(curr[b * BQ + col]);                     // matched pred
    float4 T = xyxy_filtered(prev[b * BQ + tid], s.y, s.x);  // target
    float x1 = P.x, y1 = P.y, x2 = P.z, y2 = P.w;
    float xg1 = T.x, yg1 = T.y, xg2 = T.z, yg2 = T.w;
    float iw = fmaxf(fminf(x2, xg2) - fmaxf(x1, xg1), 0.0f);
    float ih = fmaxf(fminf(y2, yg2) - fmaxf(y1, yg1), 0.0f);
    float inter = iw * ih;
    float uni = (x2 - x1) * (y2 - y1) + (xg2 - xg1) * (yg2 - yg1) - inter;
    float iou = inter / (uni + EPSF);
    float cw = fmaxf(x2, xg2) - fminf(x1, xg1);
    float ch = fmaxf(y2, yg2) - fminf(y1, yg1);
    float c2 = cw * cw + ch * ch + EPSF;
    float dx = x1 + x2 - xg1 - xg2;
    float dy = y1 + y2 - yg1 - yg2;
    float d2 = (dx * dx + dy * dy) * 0.25f;
    float dv = atanf((xg2 - xg1) / (yg2 - yg1)) - atanf((x2 - x1) / (y2 - y1));
    float v = C4PI * dv * dv;
    float alpha = v / (1.0f - iou + v + EPSF);
    float sres = 1.0f - iou + d2 / c2 + alpha * v;

    // warp-shuffle reduction (fixed order: deterministic)
#pragma unroll
    for (int o = 16; o > 0; o >>= 1) sres += __shfl_down_sync(0xffffffffu, sres, o);
    if ((tid & 31) == 0) swr[tid >> 5] = sres;
    __syncthreads();
    if (tid < 32) {
        float v2 = (tid < 16) ? swr[tid] : 0.0f;
#pragma unroll
        for (int o = 8; o > 0; o >>= 1) v2 += __shfl_down_sync(0xffffffffu, v2, o);
        if (tid == 0) {
            g_part[b] = v2;
            __threadfence();
            unsigned done = atomicAdd(&g_ctr, 1u);
            if (done == NB - 1) {
                __threadfence();
                float tot = 0.0f;
                for (int k = 0; k < NB; k++) tot += g_part[k];   // fixed order: deterministic
                out[0] = tot / (float)(NB * BQ);
                g_ctr = 0u;   // self-reset for graph replay
            }
        }
    }
}

// ---------------- launch ----------------
extern "C" void kernel_launch(void* const* d_in, const int* in_sizes, int n_in,
                              void* d_out, int out_size) {
    const float4* prev  = (const float4*)d_in[0];
    // d_in[1] prev_logits: dead code (innovation == 0 exactly)
    const float4* curr  = (const float4*)d_in[2];
    const float2* sizes = (const float2*)d_in[3];
    // d_in[4..6] std weights / log_q_diag: dead code for the same reason

    k_fused<<<dim3(BLKS_PER_B, NB), BQ>>>(prev, curr, sizes, (float*)d_out);
}

// round 14
// speedup vs baseline: 1.1800x; 1.1800x over previous
#include <cuda_runtime.h>
#include <cuda_bf16.h>

#define NB 8
#define BQ 512
#define EPSF 1e-7f
#define ROWS_PER_BLK 32
#define BLKS_PER_B (BQ / ROWS_PER_BLK)   // 16

typedef unsigned long long u64;

// ---------------- device scratch (no allocations allowed) ----------------
__device__ u64    g_ones[NB * BQ * 8];   // cost bitset: bit j of row i set iff gl[b,i,j] < 0.2
__device__ u64    g_info[NB * BQ];       // per-row: n(3b) | c0..c3 (10b each) | diag<<43
__device__ float  g_diag[NB * BLKS_PER_B]; // per-block diagonal-ciou partial sums
__device__ float  g_part[NB];            // per-batch totals
__device__ unsigned g_ctr;               // completion counter

// general-JV fallback scratch (practically never used)
__device__ int   fbU[NB][BQ + 1], fbV[NB][BQ + 1], fbMinv[NB][BQ + 1];
__device__ short fbWay[NB][BQ + 1], fbP1[NB][BQ + 1];
__device__ unsigned char fbUsed[NB][BQ + 1];

// Kalman filter is an exact identity on the mean: filtered = (prev*scale)/scale
__device__ __forceinline__ float4 xyxy_filtered(float4 pb, float W, float H) {
    float f0 = (pb.x * W) / W;
    float f1 = (pb.y * H) / H;
    float f2 = (pb.z * W) / W;
    float f3 = (pb.w * H) / H;
    return make_float4(f0 - 0.5f * f2, f1 - 0.5f * f3, f0 + 0.5f * f2, f1 + 0.5f * f3);
}
__device__ __forceinline__ float4 xyxy(float4 v) {
    return make_float4(v.x - 0.5f * v.z, v.y - 0.5f * v.w, v.x + 0.5f * v.z, v.y + 0.5f * v.w);
}

__device__ __forceinline__ float ciou_term(float4 P, float4 T) {
    const float C4PI = (float)(4.0 / (3.14159265358979323846 * 3.14159265358979323846));
    float x1 = P.x, y1 = P.y, x2 = P.z, y2 = P.w;
    float xg1 = T.x, yg1 = T.y, xg2 = T.z, yg2 = T.w;
    float iw = fmaxf(fminf(x2, xg2) - fmaxf(x1, xg1), 0.0f);
    float ih = fmaxf(fminf(y2, yg2) - fmaxf(y1, yg1), 0.0f);
    float inter = iw * ih;
    float uni = (x2 - x1) * (y2 - y1) + (xg2 - xg1) * (yg2 - yg1) - inter;
    float iou = inter / (uni + EPSF);
    float cw = fmaxf(x2, xg2) - fminf(x1, xg1);
    float ch = fmaxf(y2, yg2) - fminf(y1, yg1);
    float c2 = cw * cw + ch * ch + EPSF;
    float dx = x1 + x2 - xg1 - xg2;
    float dy = y1 + y2 - yg1 - yg2;
    float d2 = (dx * dx + dy * dy) * 0.25f;
    float dv = atanf((xg2 - xg1) / (yg2 - yg1)) - atanf((x2 - x1) / (y2 - y1));
    float v = C4PI * dv * dv;
    float alpha = v / (1.0f - iou + v + EPSF);
    return 1.0f - iou + d2 / c2 + alpha * v;
}

// ---------------- kernel 1: cost bitset + row info + diagonal ciou partials ----------------
__global__ void __launch_bounds__(BQ) k_cost(const float4* __restrict__ prev,
                                             const float4* __restrict__ curr,
                                             const float2* __restrict__ sizes) {
    int b = blockIdx.y;
    int i0 = blockIdx.x * ROWS_PER_BLK;
    int j = threadIdx.x;
    if (blockIdx.x == 0 && b == 0 && j == 0) g_ctr = 0u;
    __shared__ float4 sa[ROWS_PER_BLK];
    __shared__ float  sArea[ROWS_PER_BLK];
    __shared__ unsigned sMask[ROWS_PER_BLK * 16];
    float2 s = sizes[b];
    if (j < ROWS_PER_BLK) {
        float4 a = xyxy(curr[b * BQ + i0 + j]);
        sa[j] = a;
        sArea[j] = (a.z - a.x) * (a.w - a.y);
    }
    float4 c = xyxy_filtered(prev[b * BQ + j], s.y, s.x);
    float area_b = (c.z - c.x) * (c.w - c.y);
    __syncthreads();
    unsigned lane = j & 31, warp = j >> 5;
#pragma unroll 4
    for (int r = 0; r < ROWS_PER_BLK; r++) {
        float4 a = sa[r];
        float area_a = sArea[r];
        float ltx = fmaxf(a.x, c.x), lty = fmaxf(a.y, c.y);
        float rbx = fminf(a.z, c.z), rby = fminf(a.w, c.w);
        float wx = fmaxf(rbx - ltx, 0.0f), wy = fmaxf(rby - lty, 0.0f);
        float I = wx * wy;
        float U = area_a + area_b - I;
        float p = U + EPSF;
        // necessary condition (C >= U): pred => I > 0.8*p; 0.79 slack absorbs rounding
        unsigned anyb = __ballot_sync(0xffffffffu, I > 0.79f * p);
        unsigned m = 0u;
        if (anyb) {   // warp-uniform
            float lcx = fminf(a.x, c.x), lcy = fminf(a.y, c.y);
            float rcx = fmaxf(a.z, c.z), rcy = fmaxf(a.w, c.w);
            float C = (rcx - lcx) * (rcy - lcy);
            float q = C + EPSF;
            bool pred = (I * q - (C - U) * p) > (0.8f * p) * q;
            m = __ballot_sync(0xffffffffu, pred);
        }
        if (lane == 0) {
            sMask[r * 16 + warp] = m;
            ((unsigned*)g_ones)[((size_t)(b * BQ + i0 + r)) * 16 + warp] = m;
        }
    }
    __syncthreads();
    if (j < ROWS_PER_BLK) {
        // (warp 0 only) pack row info
        int gi = i0 + j;
        int n = 0, c0v = 0, c1v = 0, c2v = 0, c3v = 0;
#pragma unroll
        for (int k = 0; k < 16; k++) {
            unsigned x = sMask[j * 16 + k];
            while (x) {
                int cc = (k << 5) + __ffs(x) - 1;
                if (n == 0) c0v = cc; else if (n == 1) c1v = cc;
                else if (n == 2) c2v = cc; else if (n == 3) c3v = cc;
                n++;
                x &= x - 1;
            }
        }
        if (n > 4) n = 5;
        u64 diag = (u64)((sMask[j * 16 + (gi >> 5)] >> (gi & 31)) & 1u);
        g_info[b * BQ + gi] = (u64)n | ((u64)c0v << 3) | ((u64)c1v << 13)
                            | ((u64)c2v << 23) | ((u64)c3v << 33) | (diag << 43);
        // diagonal ciou term for row gi (identity-assignment precompute)
        float4 T = xyxy_filtered(prev[b * BQ + gi], s.y, s.x);
        float term = ciou_term(sa[j], T);
#pragma unroll
        for (int o = 16; o > 0; o >>= 1) term += __shfl_down_sync(0xffffffffu, term, o);
        if (j == 0) g_diag[b * BLKS_PER_B + blockIdx.x] = term;
    }
}

// ---------------- kernel 2: Hungarian (exact JV) + ciou corrections ----------------
// Parallel result: every non-diagonal row has p[i]=i with no side effects.
// Serial work: diagonal rows only (swap closed form), takeover machinery for edge cases.
__global__ void __launch_bounds__(BQ) k_match(const float4* __restrict__ prev,
                                              const float4* __restrict__ curr,
                                              const float2* __restrict__ sizes,
                                              float* __restrict__ out) {
    int b = blockIdx.x, tid = threadIdx.x;
    __shared__ u64 sInfo[BQ];              // per-row packed info
    __shared__ u64 sDiag[8];               // diagonal-bit mask
    __shared__ u64 fMask[8];               // free-column mask (takeover only)
    __shared__ short p_[BQ];               // p_[col] = assigned row
    __shared__ short colOfRow[BQ];
    __shared__ unsigned wayTag[BQ];        // takeover walk scratch
    __shared__ float swr[16];

    const u64* ones = g_ones + (size_t)b * BQ * 8;

    u64 info = g_info[b * BQ + tid];       // one coalesced LDG.64 (L2-hot)
    sInfo[tid] = info;
    p_[tid] = (short)tid;                  // default: identity (exact for all non-diag rows)
    wayTag[tid] = 0u;
    {
        bool diag = ((info >> 43) & 1ULL) != 0ULL;
        unsigned bal = __ballot_sync(0xffffffffu, diag);
        if ((tid & 31) == 0) ((unsigned*)sDiag)[tid >> 5] = bal;
    }
    __syncthreads();

    if (tid == 0) {
        int toRow = -1;
        // ---- serial: diagonal rows only ----
        for (int w = 0; w < 8 && toRow < 0; w++) {
            u64 m = sDiag[w];
            while (m) {
                int i = (w << 6) + __ffsll((long long)m) - 1;
                m &= m - 1;
                u64 ri = sInfo[i];
                int ni = (int)(ri & 7u);
                if (ni >= 5) { toRow = i; break; }
                int i0c = (int)((ri >> 3) & 1023u);
                int i1c = (int)((ri >> 13) & 1023u);
                int i2c = (int)((ri >> 23) & 1023u);
                int i3c = (int)((ri >> 33) & 1023u);
                // a = first column in 0..4 not in S (list sorted ascending)
                int a = 0;
                if (i0c == 0) {
                    a = 1;
                    if (ni > 1 && i1c == 1) { a = 2;
                        if (ni > 2 && i2c == 2) { a = 3;
                            if (ni > 3 && i3c == 3) a = 4; } }
                }
                if (a >= i) { toRow = i; break; }      // partner col not yet assigned
                int h = p_[a];                          // current holder of col a
                u64 hi = sInfo[h];
                int nh = (int)(hi & 7u);
                if (nh >= 5) { toRow = i; break; }
                int h0 = (int)((hi >> 3) & 1023u);
                int h1 = (int)((hi >> 13) & 1023u);
                int h2 = (int)((hi >> 23) & 1023u);
                int h3 = (int)((hi >> 33) & 1023u);
                bool inter = false;
                if (nh > 0) inter |= (i0c == h0) | (ni > 1 && i1c == h0) | (ni > 2 && i2c == h0) | (ni > 3 && i3c == h0);
                if (nh > 1) inter |= (i0c == h1) | (ni > 1 && i1c == h1) | (ni > 2 && i2c == h1) | (ni > 3 && i3c == h1);
                if (nh > 2) inter |= (i0c == h2) | (ni > 1 && i1c == h2) | (ni > 2 && i2c == h2) | (ni > 3 && i3c == h2);
                if (nh > 3) inter |= (i0c == h3) | (ni > 1 && i1c == h3) | (ni > 2 && i2c == h3) | (ni > 3 && i3c == h3);
                if (inter) { toRow = i; break; }
                // exact closed form of the walk for a conforming diagonal row: swap
                p_[a] = (short)i;
                p_[i] = (short)h;
            }
        }

        if (toRow >= 0) {
            // ================= serial takeover from row toRow (exact R8 machinery) =================
            for (int cc = toRow; cc < BQ; cc++) p_[cc] = -1;
            int tw = toRow >> 6;
            for (int w = 0; w < 8; w++)
                fMask[w] = (w < tw) ? 0ULL : (w == tw ? (~0ULL << (toRow & 63)) : ~0ULL);
            int w0 = tw;
            u64 fw = fMask[w0];
            int p0 = -1, p0n = 0, p0c0 = 0, p0c1 = 0, p0c2 = 0, p0c3 = 0;
            if (toRow > 0) {
                p0 = p_[0];
                u64 ri = sInfo[p0];
                p0n = (int)(ri & 7u);
                p0c0 = (int)((ri >> 3) & 1023u); p0c1 = (int)((ri >> 13) & 1023u);
                p0c2 = (int)((ri >> 23) & 1023u); p0c3 = (int)((ri >> 33) & 1023u);
            }
            int genFb = 0;
            for (int i = toRow; i < BQ && !genFb; i++) {
                u64 ii = sInfo[i];
                int n = (int)(ii & 7u);
                if (n == 0) {
                    while (!fw) { fMask[w0] = 0ULL; fw = fMask[++w0]; }
                    int F = (w0 << 6) + __ffsll((long long)fw) - 1;
                    fw &= fw - 1;
                    p_[F] = (short)i;
                    if (F == 0) { p0 = i; p0n = 0; }
                    continue;
                }
                int c0 = (int)((ii >> 3) & 1023u);
                int c1 = (int)((ii >> 13) & 1023u);
                int c2 = (int)((ii >> 23) & 1023u);
                int c3 = (int)((ii >> 33) & 1023u);
                if (n <= 4 && c0 != 0 && p0 >= 0 && p0n <= 4) {
                    bool inter = false;
                    if (p0n > 0) inter |= (c0 == p0c0) | (n > 1 && c1 == p0c0) | (n > 2 && c2 == p0c0) | (n > 3 && c3 == p0c0);
                    if (p0n > 1) inter |= (c0 == p0c1) | (n > 1 && c1 == p0c1) | (n > 2 && c2 == p0c1) | (n > 3 && c3 == p0c1);
                    if (p0n > 2) inter |= (c0 == p0c2) | (n > 1 && c1 == p0c2) | (n > 2 && c2 == p0c2) | (n > 3 && c3 == p0c2);
                    if (p0n > 3) inter |= (c0 == p0c3) | (n > 1 && c1 == p0c3) | (n > 2 && c2 == p0c3) | (n > 3 && c3 == p0c3);
                    if (!inter) {
                        while (!fw) { fMask[w0] = 0ULL; fw = fMask[++w0]; }
                        int F = (w0 << 6) + __ffsll((long long)fw) - 1;
                        fw &= fw - 1;
                        bool FinS = (F == c0) | (n > 1 && F == c1) | (n > 2 && F == c2) | (n > 3 && F == c3);
                        if (FinS) {
                            p_[F] = (short)p0;
                            p_[0] = (short)i;
                            p0 = i; p0n = n;
                            p0c0 = c0; p0c1 = c1; p0c2 = c2; p0c3 = c3;
                        } else {
                            p_[F] = (short)i;
                        }
                        continue;
                    }
                }
                // slow path: exact JV walk (delta==0 regime), bitsets from L2
                fMask[w0] = fw;
                const u64* rowi = ones + (size_t)i * 8;
                u64 nz[8], U[8];
#pragma unroll
                for (int w = 0; w < 8; w++) { nz[w] = rowi[w]; U[w] = 0ULL; }
                unsigned ep = (unsigned)(i + 1);
                int jf = -1; bool fb = false;
                while (true) {
                    u64 any = 0ULL;
#pragma unroll
                    for (int w = 0; w < 8; w++) any |= nz[w];
                    if (!any) {
#pragma unroll
                        for (int w = 0; w < 8; w++)
                            if (jf < 0 && fMask[w]) jf = w * 64 + __ffsll((long long)fMask[w]) - 1;
                        break;
                    }
                    int j1 = -1;
#pragma unroll
                    for (int w = 0; w < 8; w++) {
                        u64 cnd = ~(U[w] | nz[w]);
                        if (j1 < 0 && cnd) j1 = w * 64 + __ffsll((long long)cnd) - 1;
                    }
                    if (j1 < 0) { fb = true; break; }      // delta>0 would be needed
                    if (p_[j1] < 0) { jf = j1; break; }    // reached a free column
                    U[j1 >> 6] |= 1ULL << (j1 & 63);
                    const u64* rowr = ones + (size_t)p_[j1] * 8;
#pragma unroll
                    for (int w = 0; w < 8; w++) {
                        u64 rw = rowr[w];
                        u64 d = nz[w] & ~rw;
                        while (d) {
                            int cc = w * 64 + __ffsll((long long)d) - 1;
                            wayTag[cc] = (ep << 16) | (unsigned)j1;
                            d &= d - 1;
                        }
                        nz[w] &= rw;
                    }
                }
                if (fb) { genFb = 1; break; }
                fMask[jf >> 6] &= ~(1ULL << (jf & 63));
                int j = jf;
                while (true) {
                    unsigned tg = wayTag[j];
                    if ((tg >> 16) == ep) { int w = (int)(tg & 0xffffu); p_[j] = p_[w]; j = w; }
                    else { p_[j] = (short)i; break; }
                }
                fw = fMask[w0];
                {
                    int r = p_[0];
                    p0 = r;
                    if (r >= 0) {
                        u64 ri = sInfo[r];
                        p0n = (int)(ri & 7u);
                        p0c0 = (int)((ri >> 3) & 1023u); p0c1 = (int)((ri >> 13) & 1023u);
                        p0c2 = (int)((ri >> 23) & 1023u); p0c3 = (int)((ri >> 33) & 1023u);
                    }
                }
            }

            if (genFb) {
                // ---- general JV from scratch (exact numpy semantics) ----
                int*   u_ = fbU[b]; int* v_ = fbV[b]; int* minv_ = fbMinv[b];
                short* way2 = fbWay[b]; short* p1 = fbP1[b];
                unsigned char* used_ = fbUsed[b];
                for (int j = 0; j <= BQ; j++) { u_[j] = 0; v_[j] = 0; p1[j] = 0; }
                const int INF = 0x3f3f3f3f;
                for (int i = 1; i <= BQ; i++) {
                    p1[0] = (short)i; int j0 = 0;
                    for (int j = 0; j <= BQ; j++) { minv_[j] = INF; used_[j] = 0; }
                    while (true) {
                        used_[j0] = 1;
                        int i0p = p1[j0];
                        int d = INF, j1 = -1;
                        int ui = u_[i0p];
                        const u64* rr = ones + (size_t)(i0p - 1) * 8;
                        for (int j = 1; j <= BQ; j++) {
                            if (used_[j]) continue;
                            int cc = j - 1;
                            int cbit = (int)((rr[cc >> 6] >> (cc & 63)) & 1ULL);
                            int cur = cbit - ui - v_[j];
                            if (cur < minv_[j]) { minv_[j] = cur; way2[j] = (short)j0; }
                            if (minv_[j] < d) { d = minv_[j]; j1 = j; }
                        }
                        for (int j = 0; j <= BQ; j++) {
                            if (used_[j]) { u_[p1[j]] += d; v_[j] -= d; }
                            else minv_[j] -= d;
                        }
                        j0 = j1;
                        if (p1[j0] == 0) break;
                    }
                    while (j0) { int jw = way2[j0]; p1[j0] = p1[jw]; j0 = jw; }
                }
                for (int j = 0; j < BQ; j++) p_[j] = (short)(p1[j + 1] - 1);
            }
        }
    }
    __syncthreads();
    colOfRow[p_[tid]] = (short)tid;
    __syncthreads();

    // ---- ciou corrections: only rows whose assigned col differs from identity ----
    float2 s = sizes[b];
    int col = colOfRow[tid];
    float delta = 0.0f;
    if (col != tid) {
        float4 T  = xyxy_filtered(prev[b * BQ + tid], s.y, s.x);
        float4 P1 = xyxy(curr[b * BQ + col]);
        float4 P0 = xyxy(curr[b * BQ + tid]);
        delta = ciou_term(P1, T) - ciou_term(P0, T);
    }
    // deterministic block reduction of deltas
#pragma unroll
    for (int o = 16; o > 0; o >>= 1) delta += __shfl_down_sync(0xffffffffu, delta, o);
    if ((tid & 31) == 0) swr[tid >> 5] = delta;
    __syncthreads();
    if (tid < 32) {
        float v2 = (tid < 16) ? swr[tid] : 0.0f;
#pragma unroll
        for (int o = 8; o > 0; o >>= 1) v2 += __shfl_down_sync(0xffffffffu, v2, o);
        if (tid == 0) {
            float tot = v2;
#pragma unroll
            for (int k = 0; k < BLKS_PER_B; k++) tot += g_diag[b * BLKS_PER_B + k]; // fixed order
            g_part[b] = tot;
            __threadfence();
            unsigned done = atomicAdd(&g_ctr, 1u);
            if (done == NB - 1) {
                __threadfence();
                float t2 = 0.0f;
                for (int k = 0; k < NB; k++) t2 += g_part[k];   // fixed order: deterministic
                out[0] = t2 / (float)(NB * BQ);
            }
        }
    }
}

// ---------------- launch ----------------
extern "C" void kernel_launch(void* const* d_in, const int* in_sizes, int n_in,
                              void* d_out, int out_size) {
    const float4* prev  = (const float4*)d_in[0];
    // d_in[1] prev_logits: dead code (innovation == 0 exactly)
    const float4* curr  = (const float4*)d_in[2];
    const float2* sizes = (const float2*)d_in[3];
    // d_in[4..6] std weights / log_q_diag: dead code for the same reason

    k_cost<<<dim3(BLKS_PER_B, NB), BQ>>>(prev, curr, sizes);
    k_match<<<NB, BQ>>>(prev, curr, sizes, (float*)d_out);
}